// round 1
// baseline (speedup 1.0000x reference)
#include <cuda_runtime.h>
#include <math.h>

// Problem constants
#define B_ROWS   8192
#define EXP_DIM  1024
#define DICT     4096
#define N_ITERS  20
#define STEP_SZ  0.1f
#define THRESH   0.01f   // REG * STEP
#define K_SPARSE 409

// Tiling
#define TM 128
#define TN 128
#define TK 16
#define SMEM_LD 132   // padded row length (floats), 16B-aligned (132*4=528)

// Scratch: residual [8192 x 1024] fp32 (allocation-free device global)
__device__ float g_resid[(size_t)B_ROWS * EXP_DIM];

// ---------------------------------------------------------------------------
// GEMM1: resid[M=8192, N=1024] = X - alpha[8192,4096] @ D[4096,1024]   (NN)
// ---------------------------------------------------------------------------
__global__ __launch_bounds__(256, 2)
void gemm1_kernel(const float* __restrict__ alpha,
                  const float* __restrict__ Dmat,
                  const float* __restrict__ X)
{
    __shared__ float As[TK][SMEM_LD];
    __shared__ float Bs[TK][SMEM_LD];

    const int tid = threadIdx.x;
    const int tx = tid & 15;        // 0..15  -> col group
    const int ty = tid >> 4;        // 0..15  -> row group
    const int m0 = blockIdx.y * TM;
    const int n0 = blockIdx.x * TN;

    const int am  = tid >> 2;       // 0..63 row for A loads
    const int akq = tid & 3;        // 0..3  k-quad for A loads
    const int bk  = tid >> 5;       // 0..7  k row for B loads
    const int bnq = tid & 31;       // 0..31 n-quad for B loads

    float acc[8][8];
#pragma unroll
    for (int i = 0; i < 8; i++)
#pragma unroll
        for (int j = 0; j < 8; j++) acc[i][j] = 0.0f;

    for (int kt = 0; kt < DICT; kt += TK) {
        // A tile (transpose on store): As[k][m] = alpha[m0+m, kt+k]
#pragma unroll
        for (int r = 0; r < 2; r++) {
            int mm = am + r * 64;
            float4 v = *reinterpret_cast<const float4*>(
                alpha + (size_t)(m0 + mm) * DICT + kt + akq * 4);
            As[akq * 4 + 0][mm] = v.x;
            As[akq * 4 + 1][mm] = v.y;
            As[akq * 4 + 2][mm] = v.z;
            As[akq * 4 + 3][mm] = v.w;
        }
        // B tile (direct): Bs[k][n] = D[kt+k, n0+n]
#pragma unroll
        for (int r = 0; r < 2; r++) {
            int kk = bk + r * 8;
            float4 v = *reinterpret_cast<const float4*>(
                Dmat + (size_t)(kt + kk) * EXP_DIM + n0 + bnq * 4);
            *reinterpret_cast<float4*>(&Bs[kk][bnq * 4]) = v;
        }
        __syncthreads();

#pragma unroll
        for (int k = 0; k < TK; k++) {
            float a[8], b[8];
            *reinterpret_cast<float4*>(&a[0]) = *reinterpret_cast<const float4*>(&As[k][ty * 8]);
            *reinterpret_cast<float4*>(&a[4]) = *reinterpret_cast<const float4*>(&As[k][ty * 8 + 4]);
            *reinterpret_cast<float4*>(&b[0]) = *reinterpret_cast<const float4*>(&Bs[k][tx * 8]);
            *reinterpret_cast<float4*>(&b[4]) = *reinterpret_cast<const float4*>(&Bs[k][tx * 8 + 4]);
#pragma unroll
            for (int i = 0; i < 8; i++)
#pragma unroll
                for (int j = 0; j < 8; j++) acc[i][j] = fmaf(a[i], b[j], acc[i][j]);
        }
        __syncthreads();
    }

    // Epilogue: resid = X - acc
#pragma unroll
    for (int i = 0; i < 8; i++) {
        int row = m0 + ty * 8 + i;
#pragma unroll
        for (int j = 0; j < 8; j += 4) {
            int col = n0 + tx * 8 + j;
            float4 xv = *reinterpret_cast<const float4*>(X + (size_t)row * EXP_DIM + col);
            float4 o;
            o.x = xv.x - acc[i][j + 0];
            o.y = xv.y - acc[i][j + 1];
            o.z = xv.z - acc[i][j + 2];
            o.w = xv.w - acc[i][j + 3];
            *reinterpret_cast<float4*>(&g_resid[(size_t)row * EXP_DIM + col]) = o;
        }
    }
}

// ---------------------------------------------------------------------------
// GEMM2: alpha[8192,4096] = shrink(alpha + STEP * resid[8192,1024] @ D^T) (NT)
// FIRST=true: treat alpha_old as 0 (skips the read; also serves as init).
// ---------------------------------------------------------------------------
template <bool FIRST>
__global__ __launch_bounds__(256, 2)
void gemm2_kernel(const float* __restrict__ Dmat,
                  float* __restrict__ alpha)
{
    __shared__ float As[TK][SMEM_LD];
    __shared__ float Bs[TK][SMEM_LD];

    const int tid = threadIdx.x;
    const int tx = tid & 15;
    const int ty = tid >> 4;
    const int m0 = blockIdx.y * TM;
    const int n0 = blockIdx.x * TN;

    const int am  = tid >> 2;   // row (or n-row for B) 0..63
    const int akq = tid & 3;    // k-quad 0..3

    float acc[8][8];
#pragma unroll
    for (int i = 0; i < 8; i++)
#pragma unroll
        for (int j = 0; j < 8; j++) acc[i][j] = 0.0f;

    for (int kt = 0; kt < EXP_DIM; kt += TK) {
        // A tile: As[k][m] = resid[m0+m, kt+k]
#pragma unroll
        for (int r = 0; r < 2; r++) {
            int mm = am + r * 64;
            float4 v = *reinterpret_cast<const float4*>(
                &g_resid[(size_t)(m0 + mm) * EXP_DIM + kt + akq * 4]);
            As[akq * 4 + 0][mm] = v.x;
            As[akq * 4 + 1][mm] = v.y;
            As[akq * 4 + 2][mm] = v.z;
            As[akq * 4 + 3][mm] = v.w;
        }
        // B tile (transposed access): Bs[k][n] = D[n0+n, kt+k]
#pragma unroll
        for (int r = 0; r < 2; r++) {
            int nn = am + r * 64;
            float4 v = *reinterpret_cast<const float4*>(
                Dmat + (size_t)(n0 + nn) * EXP_DIM + kt + akq * 4);
            Bs[akq * 4 + 0][nn] = v.x;
            Bs[akq * 4 + 1][nn] = v.y;
            Bs[akq * 4 + 2][nn] = v.z;
            Bs[akq * 4 + 3][nn] = v.w;
        }
        __syncthreads();

#pragma unroll
        for (int k = 0; k < TK; k++) {
            float a[8], b[8];
            *reinterpret_cast<float4*>(&a[0]) = *reinterpret_cast<const float4*>(&As[k][ty * 8]);
            *reinterpret_cast<float4*>(&a[4]) = *reinterpret_cast<const float4*>(&As[k][ty * 8 + 4]);
            *reinterpret_cast<float4*>(&b[0]) = *reinterpret_cast<const float4*>(&Bs[k][tx * 8]);
            *reinterpret_cast<float4*>(&b[4]) = *reinterpret_cast<const float4*>(&Bs[k][tx * 8 + 4]);
#pragma unroll
            for (int i = 0; i < 8; i++)
#pragma unroll
                for (int j = 0; j < 8; j++) acc[i][j] = fmaf(a[i], b[j], acc[i][j]);
        }
        __syncthreads();
    }

    // Epilogue: v = alpha_old + STEP*acc; alpha = sign(v)*max(|v|-THRESH, 0)
#pragma unroll
    for (int i = 0; i < 8; i++) {
        int row = m0 + ty * 8 + i;
        float* cptr = alpha + (size_t)row * DICT + n0 + tx * 8;
#pragma unroll
        for (int j = 0; j < 8; j += 4) {
            float4 oldv;
            if (FIRST) { oldv.x = oldv.y = oldv.z = oldv.w = 0.0f; }
            else       { oldv = *reinterpret_cast<const float4*>(cptr + j); }
            float4 o;
            float v, s;
            v = oldv.x + STEP_SZ * acc[i][j + 0]; s = fabsf(v) - THRESH; o.x = s > 0.0f ? copysignf(s, v) : 0.0f;
            v = oldv.y + STEP_SZ * acc[i][j + 1]; s = fabsf(v) - THRESH; o.y = s > 0.0f ? copysignf(s, v) : 0.0f;
            v = oldv.z + STEP_SZ * acc[i][j + 2]; s = fabsf(v) - THRESH; o.z = s > 0.0f ? copysignf(s, v) : 0.0f;
            v = oldv.w + STEP_SZ * acc[i][j + 3]; s = fabsf(v) - THRESH; o.w = s > 0.0f ? copysignf(s, v) : 0.0f;
            *reinterpret_cast<float4*>(cptr + j) = o;
        }
    }
}

// ---------------------------------------------------------------------------
// Iter 0: resid = X (alpha == 0)
// ---------------------------------------------------------------------------
__global__ void copy_resid_kernel(const float* __restrict__ X)
{
    int i = blockIdx.x * blockDim.x + threadIdx.x;
    const int n4 = (B_ROWS * EXP_DIM) / 4;
    if (i < n4) {
        reinterpret_cast<float4*>(g_resid)[i] =
            reinterpret_cast<const float4*>(X)[i];
    }
}

// ---------------------------------------------------------------------------
// Top-k: per row, find 409th-largest |a| via 8-round nibble radix select,
// zero all entries with |a| < threshold key. One block per row.
// ---------------------------------------------------------------------------
__global__ __launch_bounds__(256)
void topk_kernel(float* __restrict__ alpha)
{
    __shared__ unsigned int keys[DICT];
    __shared__ int hist[16];
    __shared__ int s_bucket;
    __shared__ int s_remk;

    const int tid = threadIdx.x;
    float* a = alpha + (size_t)blockIdx.x * DICT;

    for (int i = tid; i < DICT; i += 256)
        keys[i] = __float_as_uint(fabsf(a[i]));
    __syncthreads();

    unsigned int prefix = 0u, mask = 0u;
    int remk = K_SPARSE;

#pragma unroll
    for (int shift = 28; shift >= 0; shift -= 4) {
        if (tid < 16) hist[tid] = 0;
        __syncthreads();
        for (int i = tid; i < DICT; i += 256) {
            unsigned int k = keys[i];
            if ((k & mask) == prefix)
                atomicAdd(&hist[(k >> shift) & 15], 1);
        }
        __syncthreads();
        if (tid == 0) {
            int r = remk;
            int b = 15;
            for (; b > 0; b--) {
                if (r - hist[b] <= 0) break;
                r -= hist[b];
            }
            s_bucket = b;
            s_remk = r;
        }
        __syncthreads();
        prefix |= ((unsigned int)s_bucket) << shift;
        mask   |= 0xFu << shift;
        remk = s_remk;
        __syncthreads();
    }

    const unsigned int t = prefix;   // key of the K_SPARSE-th largest |a|
    for (int i = tid; i < DICT; i += 256)
        if (keys[i] < t) a[i] = 0.0f;
}

// ---------------------------------------------------------------------------
// Launch
// ---------------------------------------------------------------------------
extern "C" void kernel_launch(void* const* d_in, const int* in_sizes, int n_in,
                              void* d_out, int out_size)
{
    const float* X    = (const float*)d_in[0];   // [8192, 1024]
    const float* Dmat = (const float*)d_in[1];   // [4096, 1024]
    float* alpha      = (float*)d_out;           // [8192, 4096]

    const dim3 blk(256);
    const dim3 g1(EXP_DIM / TN, B_ROWS / TM);    // ( 8, 64)
    const dim3 g2(DICT    / TN, B_ROWS / TM);    // (32, 64)

    // Iteration 0: alpha=0 -> resid = X, then first alpha update (writes all of alpha)
    {
        const int n4 = (B_ROWS * EXP_DIM) / 4;
        copy_resid_kernel<<<(n4 + 255) / 256, 256>>>(X);
        gemm2_kernel<true><<<g2, blk>>>(Dmat, alpha);
    }
    // Iterations 1..19
    for (int it = 1; it < N_ITERS; it++) {
        gemm1_kernel<<<g1, blk>>>(alpha, Dmat, X);
        gemm2_kernel<false><<<g2, blk>>>(Dmat, alpha);
    }
    // Hard top-k sparsification
    topk_kernel<<<B_ROWS, blk>>>(alpha);
}

// round 11
// speedup vs baseline: 1.7798x; 1.7798x over previous
#include <cuda_runtime.h>
#include <cstdint>
#include <math.h>

// ---------------- problem constants ----------------
#define B_ROWS   8192
#define EXP_DIM  1024
#define DICT     4096
#define N_ITERS  20
#define STEP_SZ  0.1f
#define THRESH   0.01f   // REG * STEP
#define K_SPARSE 409

// ---------------- tiling ----------------
#define TM 128
#define TN 128
#define TK 16
#define SMEM_LD 132
#define NTHREADS 256

// scratch: residual [8192 x 1024] fp32 (allocation-free device global)
__device__ float g_resid[(size_t)B_ROWS * EXP_DIM];

// ---------------- f32x2 packed helpers (Blackwell FFMA2) ----------------
typedef unsigned long long u64;

__device__ __forceinline__ u64 pack2(float lo, float hi) {
    u64 r;
    asm("mov.b64 %0, {%1, %2};" : "=l"(r) : "f"(lo), "f"(hi));
    return r;
}
__device__ __forceinline__ void unpack2(u64 v, float& lo, float& hi) {
    asm("mov.b64 {%0, %1}, %2;" : "=f"(lo), "=f"(hi) : "l"(v));
}
__device__ __forceinline__ void fma2(u64& d, u64 a, u64 b) {
    asm("fma.rn.f32x2 %0, %1, %2, %0;" : "+l"(d) : "l"(a), "l"(b));
}

// ---------------- compute core: 16 k-steps on one smem buffer ----------------
// acc[i][j]: rows ty*8+i, cols tx*8 + {2j, 2j+1}
__device__ __forceinline__ void compute_tile(const float (*As)[SMEM_LD],
                                             const float (*Bs)[SMEM_LD],
                                             u64 acc[8][4], int tx, int ty)
{
#pragma unroll
    for (int k = 0; k < TK; k++) {
        float4 av0 = *reinterpret_cast<const float4*>(&As[k][ty * 8]);
        float4 av1 = *reinterpret_cast<const float4*>(&As[k][ty * 8 + 4]);
        float4 bv0 = *reinterpret_cast<const float4*>(&Bs[k][tx * 8]);
        float4 bv1 = *reinterpret_cast<const float4*>(&Bs[k][tx * 8 + 4]);
        u64 asp[8], b2[4];
        asp[0] = pack2(av0.x, av0.x); asp[1] = pack2(av0.y, av0.y);
        asp[2] = pack2(av0.z, av0.z); asp[3] = pack2(av0.w, av0.w);
        asp[4] = pack2(av1.x, av1.x); asp[5] = pack2(av1.y, av1.y);
        asp[6] = pack2(av1.z, av1.z); asp[7] = pack2(av1.w, av1.w);
        b2[0] = pack2(bv0.x, bv0.y);  b2[1] = pack2(bv0.z, bv0.w);
        b2[2] = pack2(bv1.x, bv1.y);  b2[3] = pack2(bv1.z, bv1.w);
#pragma unroll
        for (int i = 0; i < 8; i++)
#pragma unroll
            for (int j = 0; j < 4; j++) fma2(acc[i][j], asp[i], b2[j]);
    }
}

// ---------------------------------------------------------------------------
// GEMM1: resid[8192,1024] = X - alpha[8192,4096] @ D[4096,1024]   (NN)
// ---------------------------------------------------------------------------
__global__ __launch_bounds__(NTHREADS, 2)
void gemm1_kernel(const float* __restrict__ alpha,
                  const float* __restrict__ Dmat,
                  const float* __restrict__ X)
{
    __shared__ float As[2][TK][SMEM_LD];
    __shared__ float Bs[2][TK][SMEM_LD];

    const int tid = threadIdx.x;
    const int tx = tid & 15, ty = tid >> 4;
    const int m0 = blockIdx.y * TM, n0 = blockIdx.x * TN;

    const int am  = tid >> 2;       // 0..63 row for A loads
    const int akq = tid & 3;        // 0..3  k-quad for A loads
    const int bk  = tid >> 5;       // 0..7  k row for B loads
    const int bnq = tid & 31;       // 0..31 n-quad for B loads

    u64 acc[8][4];
#pragma unroll
    for (int i = 0; i < 8; i++)
#pragma unroll
        for (int j = 0; j < 4; j++) acc[i][j] = 0ull;

    float4 pa[2], pb[2];

#define G1_LDG(kt) do {                                                           \
    _Pragma("unroll")                                                             \
    for (int r = 0; r < 2; r++) {                                                 \
        pa[r] = *reinterpret_cast<const float4*>(                                 \
            alpha + (size_t)(m0 + am + r * 64) * DICT + (kt) + akq * 4);          \
        pb[r] = *reinterpret_cast<const float4*>(                                 \
            Dmat + (size_t)((kt) + bk + r * 8) * EXP_DIM + n0 + bnq * 4);         \
    } } while (0)

#define G1_STS(buf) do {                                                          \
    _Pragma("unroll")                                                             \
    for (int r = 0; r < 2; r++) {                                                 \
        int mm = am + r * 64;                                                     \
        As[buf][akq * 4 + 0][mm] = pa[r].x;                                       \
        As[buf][akq * 4 + 1][mm] = pa[r].y;                                       \
        As[buf][akq * 4 + 2][mm] = pa[r].z;                                       \
        As[buf][akq * 4 + 3][mm] = pa[r].w;                                       \
        *reinterpret_cast<float4*>(&Bs[buf][bk + r * 8][bnq * 4]) = pb[r];        \
    } } while (0)

    G1_LDG(0);
    G1_STS(0);
    __syncthreads();

    const int nT = DICT / TK;
    for (int kt = 0; kt < nT; kt++) {
        const int buf = kt & 1;
        if (kt + 1 < nT) G1_LDG((kt + 1) * TK);
        compute_tile(As[buf], Bs[buf], acc, tx, ty);
        if (kt + 1 < nT) {
            G1_STS(1 - buf);
            __syncthreads();
        }
    }
#undef G1_LDG
#undef G1_STS

    // epilogue: resid = X - acc
#pragma unroll
    for (int i = 0; i < 8; i++) {
        int row = m0 + ty * 8 + i;
#pragma unroll
        for (int j = 0; j < 4; j += 2) {
            int col = n0 + tx * 8 + j * 2;
            float4 xv = *reinterpret_cast<const float4*>(X + (size_t)row * EXP_DIM + col);
            float a0, a1, a2, a3;
            unpack2(acc[i][j], a0, a1);
            unpack2(acc[i][j + 1], a2, a3);
            float4 o = make_float4(xv.x - a0, xv.y - a1, xv.z - a2, xv.w - a3);
            *reinterpret_cast<float4*>(&g_resid[(size_t)row * EXP_DIM + col]) = o;
        }
    }
}

// ---------------------------------------------------------------------------
// GEMM2: alpha = shrink(alpha + STEP * resid[8192,1024] @ D^T)    (NT)
// ---------------------------------------------------------------------------
template <bool FIRST>
__global__ __launch_bounds__(NTHREADS, 2)
void gemm2_kernel(const float* __restrict__ Dmat,
                  float* __restrict__ alpha)
{
    __shared__ float As[2][TK][SMEM_LD];
    __shared__ float Bs[2][TK][SMEM_LD];

    const int tid = threadIdx.x;
    const int tx = tid & 15, ty = tid >> 4;
    const int m0 = blockIdx.y * TM, n0 = blockIdx.x * TN;

    const int am  = tid >> 2;   // 0..63
    const int akq = tid & 3;    // 0..3

    u64 acc[8][4];
#pragma unroll
    for (int i = 0; i < 8; i++)
#pragma unroll
        for (int j = 0; j < 4; j++) acc[i][j] = 0ull;

    float4 pa[2], pb[2];

#define G2_LDG(kt) do {                                                           \
    _Pragma("unroll")                                                             \
    for (int r = 0; r < 2; r++) {                                                 \
        pa[r] = *reinterpret_cast<const float4*>(                                 \
            &g_resid[(size_t)(m0 + am + r * 64) * EXP_DIM + (kt) + akq * 4]);     \
        pb[r] = *reinterpret_cast<const float4*>(                                 \
            Dmat + (size_t)(n0 + am + r * 64) * EXP_DIM + (kt) + akq * 4);        \
    } } while (0)

#define G2_STS(buf) do {                                                          \
    _Pragma("unroll")                                                             \
    for (int r = 0; r < 2; r++) {                                                 \
        int mm = am + r * 64;                                                     \
        As[buf][akq * 4 + 0][mm] = pa[r].x;                                       \
        As[buf][akq * 4 + 1][mm] = pa[r].y;                                       \
        As[buf][akq * 4 + 2][mm] = pa[r].z;                                       \
        As[buf][akq * 4 + 3][mm] = pa[r].w;                                       \
        Bs[buf][akq * 4 + 0][mm] = pb[r].x;                                       \
        Bs[buf][akq * 4 + 1][mm] = pb[r].y;                                       \
        Bs[buf][akq * 4 + 2][mm] = pb[r].z;                                       \
        Bs[buf][akq * 4 + 3][mm] = pb[r].w;                                       \
    } } while (0)

    G2_LDG(0);
    G2_STS(0);
    __syncthreads();

    const int nT = EXP_DIM / TK;
    for (int kt = 0; kt < nT; kt++) {
        const int buf = kt & 1;
        if (kt + 1 < nT) G2_LDG((kt + 1) * TK);
        compute_tile(As[buf], Bs[buf], acc, tx, ty);
        if (kt + 1 < nT) {
            G2_STS(1 - buf);
            __syncthreads();
        }
    }
#undef G2_LDG
#undef G2_STS

    // epilogue: v = alpha_old + STEP*acc; alpha = sign(v)*max(|v|-THRESH, 0)
#pragma unroll
    for (int i = 0; i < 8; i++) {
        int row = m0 + ty * 8 + i;
        float* cptr = alpha + (size_t)row * DICT + n0 + tx * 8;
#pragma unroll
        for (int j = 0; j < 4; j += 2) {
            float4 oldv;
            if (FIRST) { oldv.x = oldv.y = oldv.z = oldv.w = 0.0f; }
            else       { oldv = *reinterpret_cast<const float4*>(cptr + j * 2); }
            float a0, a1, a2, a3;
            unpack2(acc[i][j], a0, a1);
            unpack2(acc[i][j + 1], a2, a3);
            float4 o;
            float v, s;
            v = oldv.x + STEP_SZ * a0; s = fabsf(v) - THRESH; o.x = s > 0.0f ? copysignf(s, v) : 0.0f;
            v = oldv.y + STEP_SZ * a1; s = fabsf(v) - THRESH; o.y = s > 0.0f ? copysignf(s, v) : 0.0f;
            v = oldv.z + STEP_SZ * a2; s = fabsf(v) - THRESH; o.z = s > 0.0f ? copysignf(s, v) : 0.0f;
            v = oldv.w + STEP_SZ * a3; s = fabsf(v) - THRESH; o.w = s > 0.0f ? copysignf(s, v) : 0.0f;
            *reinterpret_cast<float4*>(cptr + j * 2) = o;
        }
    }
}

// ---------------- iter 0: resid = X ----------------
__global__ void copy_resid_kernel(const float* __restrict__ X)
{
    int i = blockIdx.x * blockDim.x + threadIdx.x;
    const int n4 = (B_ROWS * EXP_DIM) / 4;
    if (i < n4) {
        reinterpret_cast<float4*>(g_resid)[i] =
            reinterpret_cast<const float4*>(X)[i];
    }
}

// ---------------- top-k (nibble radix select per row) ----------------
__global__ __launch_bounds__(256)
void topk_kernel(float* __restrict__ alpha)
{
    __shared__ unsigned int keys[DICT];
    __shared__ int hist[16];
    __shared__ int s_bucket;
    __shared__ int s_remk;

    const int tid = threadIdx.x;
    float* a = alpha + (size_t)blockIdx.x * DICT;

    for (int i = tid; i < DICT; i += 256)
        keys[i] = __float_as_uint(fabsf(a[i]));
    __syncthreads();

    unsigned int prefix = 0u, mask = 0u;
    int remk = K_SPARSE;

#pragma unroll
    for (int shift = 28; shift >= 0; shift -= 4) {
        if (tid < 16) hist[tid] = 0;
        __syncthreads();
        for (int i = tid; i < DICT; i += 256) {
            unsigned int k = keys[i];
            if ((k & mask) == prefix)
                atomicAdd(&hist[(k >> shift) & 15], 1);
        }
        __syncthreads();
        if (tid == 0) {
            int r = remk, b = 15;
            for (; b > 0; b--) {
                if (r - hist[b] <= 0) break;
                r -= hist[b];
            }
            s_bucket = b; s_remk = r;
        }
        __syncthreads();
        prefix |= ((unsigned int)s_bucket) << shift;
        mask   |= 0xFu << shift;
        remk = s_remk;
        __syncthreads();
    }

    const unsigned int t = prefix;
    for (int i = tid; i < DICT; i += 256)
        if (keys[i] < t) a[i] = 0.0f;
}

// ---------------- launch ----------------
extern "C" void kernel_launch(void* const* d_in, const int* in_sizes, int n_in,
                              void* d_out, int out_size)
{
    const float* X    = (const float*)d_in[0];   // [8192, 1024]
    const float* Dmat = (const float*)d_in[1];   // [4096, 1024]
    float* alpha      = (float*)d_out;           // [8192, 4096]

    const dim3 blk(NTHREADS);
    const dim3 g1(EXP_DIM / TN, B_ROWS / TM);    // ( 8, 64)
    const dim3 g2(DICT    / TN, B_ROWS / TM);    // (32, 64)

    // iter 0: alpha = 0 -> resid = X, then first alpha update
    {
        const int n4 = (B_ROWS * EXP_DIM) / 4;
        copy_resid_kernel<<<(n4 + 255) / 256, 256>>>(X);
        gemm2_kernel<true><<<g2, blk>>>(Dmat, alpha);
    }
    // iterations 1..19
    for (int it = 1; it < N_ITERS; it++) {
        gemm1_kernel<<<g1, blk>>>(alpha, Dmat, X);
        gemm2_kernel<false><<<g2, blk>>>(Dmat, alpha);
    }
    // hard top-k sparsification
    topk_kernel<<<B_ROWS, blk>>>(alpha);
}

// round 12
// speedup vs baseline: 2.0071x; 1.1277x over previous
#include <cuda_runtime.h>
#include <cstdint>
#include <math.h>

// ---------------- problem constants ----------------
#define B_ROWS   8192
#define EXP_DIM  1024
#define DICT     4096
#define N_ITERS  20
#define STEP_SZ  0.1f
#define THRESH   0.01f   // REG * STEP
#define K_SPARSE 409

// ---------------- tiling ----------------
#define TM 256
#define TN 128
#define TK 16
#define ALD 256          // A smem leading dim (floats), 1024B rows, 16B aligned
#define BLD 128          // B smem leading dim (floats)
#define NTHREADS 256

// scratch: residual [8192 x 1024] fp32 (allocation-free device global)
__device__ float g_resid[(size_t)B_ROWS * EXP_DIM];

// ---------------- f32x2 packed helpers (Blackwell FFMA2) ----------------
typedef unsigned long long u64;

__device__ __forceinline__ u64 pack2(float lo, float hi) {
    u64 r;
    asm("mov.b64 %0, {%1, %2};" : "=l"(r) : "f"(lo), "f"(hi));
    return r;
}
__device__ __forceinline__ void unpack2(u64 v, float& lo, float& hi) {
    asm("mov.b64 {%0, %1}, %2;" : "=f"(lo), "=f"(hi) : "l"(v));
}
__device__ __forceinline__ void fma2(u64& d, u64 a, u64 b) {
    asm("fma.rn.f32x2 %0, %1, %2, %0;" : "+l"(d) : "l"(a), "l"(b));
}

// ---------------- compute core: 16 k-steps on one smem buffer ----------------
// Thread tile 16(M) x 8(N). acc[p][j]: rows ty*16 + {2p, 2p+1}, col tx*8 + j.
// A fragments are native u64 pairs (consecutive m) -> no packs.
__device__ __forceinline__ void compute_tile(const float (*As)[ALD],
                                             const float (*Bs)[BLD],
                                             u64 acc[8][8], int tx, int ty)
{
#pragma unroll
    for (int k = 0; k < TK; k++) {
        const ulonglong2* pA = reinterpret_cast<const ulonglong2*>(&As[k][ty * 16]);
        u64 ap[8];
        ulonglong2 t0 = pA[0], t1 = pA[1], t2 = pA[2], t3 = pA[3];
        ap[0] = t0.x; ap[1] = t0.y; ap[2] = t1.x; ap[3] = t1.y;
        ap[4] = t2.x; ap[5] = t2.y; ap[6] = t3.x; ap[7] = t3.y;

        float4 bv0 = *reinterpret_cast<const float4*>(&Bs[k][tx * 8]);
        float4 bv1 = *reinterpret_cast<const float4*>(&Bs[k][tx * 8 + 4]);
        u64 bd[8];
        bd[0] = pack2(bv0.x, bv0.x); bd[1] = pack2(bv0.y, bv0.y);
        bd[2] = pack2(bv0.z, bv0.z); bd[3] = pack2(bv0.w, bv0.w);
        bd[4] = pack2(bv1.x, bv1.x); bd[5] = pack2(bv1.y, bv1.y);
        bd[6] = pack2(bv1.z, bv1.z); bd[7] = pack2(bv1.w, bv1.w);

#pragma unroll
        for (int p = 0; p < 8; p++)
#pragma unroll
            for (int j = 0; j < 8; j++) fma2(acc[p][j], ap[p], bd[j]);
    }
}

// ---------------------------------------------------------------------------
// GEMM1: resid[8192,1024] = X - alpha[8192,4096] @ D[4096,1024]   (NN)
// ---------------------------------------------------------------------------
__global__ __launch_bounds__(NTHREADS, 1)
void gemm1_kernel(const float* __restrict__ alpha,
                  const float* __restrict__ Dmat,
                  const float* __restrict__ X)
{
    __shared__ float As[2][TK][ALD];
    __shared__ float Bs[2][TK][BLD];

    const int tid = threadIdx.x;
    const int tx = tid & 15, ty = tid >> 4;
    const int m0 = blockIdx.y * TM, n0 = blockIdx.x * TN;

    const int arow = tid >> 2;      // 0..63  (+r*64) A row
    const int akq  = tid & 3;       // 0..3   A k-quad
    const int bkk  = tid >> 5;      // 0..7   (+r*8) B k row
    const int bnq  = tid & 31;      // 0..31  B n-quad

    u64 acc[8][8];
#pragma unroll
    for (int p = 0; p < 8; p++)
#pragma unroll
        for (int j = 0; j < 8; j++) acc[p][j] = 0ull;

    float4 pa[4], pb[2];

#define G1_LDG(kt) do {                                                           \
    _Pragma("unroll")                                                             \
    for (int r = 0; r < 4; r++)                                                   \
        pa[r] = *reinterpret_cast<const float4*>(                                 \
            alpha + (size_t)(m0 + arow + r * 64) * DICT + (kt) + akq * 4);        \
    _Pragma("unroll")                                                             \
    for (int r = 0; r < 2; r++)                                                   \
        pb[r] = *reinterpret_cast<const float4*>(                                 \
            Dmat + (size_t)((kt) + bkk + r * 8) * EXP_DIM + n0 + bnq * 4);        \
    } while (0)

#define G1_STS(buf) do {                                                          \
    _Pragma("unroll")                                                             \
    for (int r = 0; r < 4; r++) {                                                 \
        int mm = arow + r * 64;                                                   \
        As[buf][akq * 4 + 0][mm] = pa[r].x;                                       \
        As[buf][akq * 4 + 1][mm] = pa[r].y;                                       \
        As[buf][akq * 4 + 2][mm] = pa[r].z;                                       \
        As[buf][akq * 4 + 3][mm] = pa[r].w;                                       \
    }                                                                             \
    _Pragma("unroll")                                                             \
    for (int r = 0; r < 2; r++)                                                   \
        *reinterpret_cast<float4*>(&Bs[buf][bkk + r * 8][bnq * 4]) = pb[r];       \
    } while (0)

    G1_LDG(0);
    G1_STS(0);
    __syncthreads();

    const int nT = DICT / TK;
    for (int kt = 0; kt < nT; kt++) {
        const int buf = kt & 1;
        if (kt + 1 < nT) G1_LDG((kt + 1) * TK);
        compute_tile(As[buf], Bs[buf], acc, tx, ty);
        if (kt + 1 < nT) {
            G1_STS(1 - buf);
            __syncthreads();
        }
    }
#undef G1_LDG
#undef G1_STS

    // epilogue: resid = X - acc
#pragma unroll
    for (int p = 0; p < 8; p++) {
        float lo[8], hi[8];
#pragma unroll
        for (int j = 0; j < 8; j++) unpack2(acc[p][j], lo[j], hi[j]);
        const int r0 = m0 + ty * 16 + 2 * p;
        const int col = n0 + tx * 8;
#pragma unroll
        for (int h = 0; h < 2; h++) {
            const int row = r0 + h;
            const float* vals = h ? hi : lo;
            const float* xptr = X + (size_t)row * EXP_DIM + col;
            float* optr = &g_resid[(size_t)row * EXP_DIM + col];
#pragma unroll
            for (int j = 0; j < 8; j += 4) {
                float4 xv = *reinterpret_cast<const float4*>(xptr + j);
                float4 o = make_float4(xv.x - vals[j], xv.y - vals[j + 1],
                                       xv.z - vals[j + 2], xv.w - vals[j + 3]);
                *reinterpret_cast<float4*>(optr + j) = o;
            }
        }
    }
}

// ---------------------------------------------------------------------------
// GEMM2: alpha = shrink(alpha + STEP * resid[8192,1024] @ D^T)    (NT)
// ---------------------------------------------------------------------------
template <bool FIRST>
__global__ __launch_bounds__(NTHREADS, 1)
void gemm2_kernel(const float* __restrict__ Dmat,
                  float* __restrict__ alpha)
{
    __shared__ float As[2][TK][ALD];
    __shared__ float Bs[2][TK][BLD];

    const int tid = threadIdx.x;
    const int tx = tid & 15, ty = tid >> 4;
    const int m0 = blockIdx.y * TM, n0 = blockIdx.x * TN;

    const int arow = tid >> 2;      // 0..63 (+r*64)
    const int akq  = tid & 3;       // 0..3

    u64 acc[8][8];
#pragma unroll
    for (int p = 0; p < 8; p++)
#pragma unroll
        for (int j = 0; j < 8; j++) acc[p][j] = 0ull;

    float4 pa[4], pb[2];

#define G2_LDG(kt) do {                                                           \
    _Pragma("unroll")                                                             \
    for (int r = 0; r < 4; r++)                                                   \
        pa[r] = *reinterpret_cast<const float4*>(                                 \
            &g_resid[(size_t)(m0 + arow + r * 64) * EXP_DIM + (kt) + akq * 4]);   \
    _Pragma("unroll")                                                             \
    for (int r = 0; r < 2; r++)                                                   \
        pb[r] = *reinterpret_cast<const float4*>(                                 \
            Dmat + (size_t)(n0 + arow + r * 64) * EXP_DIM + (kt) + akq * 4);      \
    } while (0)

#define G2_STS(buf) do {                                                          \
    _Pragma("unroll")                                                             \
    for (int r = 0; r < 4; r++) {                                                 \
        int mm = arow + r * 64;                                                   \
        As[buf][akq * 4 + 0][mm] = pa[r].x;                                       \
        As[buf][akq * 4 + 1][mm] = pa[r].y;                                       \
        As[buf][akq * 4 + 2][mm] = pa[r].z;                                       \
        As[buf][akq * 4 + 3][mm] = pa[r].w;                                       \
    }                                                                             \
    _Pragma("unroll")                                                             \
    for (int r = 0; r < 2; r++) {                                                 \
        int nn = arow + r * 64;                                                   \
        if (nn < TN) {                                                            \
            Bs[buf][akq * 4 + 0][nn] = pb[r].x;                                   \
            Bs[buf][akq * 4 + 1][nn] = pb[r].y;                                   \
            Bs[buf][akq * 4 + 2][nn] = pb[r].z;                                   \
            Bs[buf][akq * 4 + 3][nn] = pb[r].w;                                   \
        }                                                                         \
    } } while (0)

    G2_LDG(0);
    G2_STS(0);
    __syncthreads();

    const int nT = EXP_DIM / TK;
    for (int kt = 0; kt < nT; kt++) {
        const int buf = kt & 1;
        if (kt + 1 < nT) G2_LDG((kt + 1) * TK);
        compute_tile(As[buf], Bs[buf], acc, tx, ty);
        if (kt + 1 < nT) {
            G2_STS(1 - buf);
            __syncthreads();
        }
    }
#undef G2_LDG
#undef G2_STS

    // epilogue: v = alpha_old + STEP*acc; alpha = sign(v)*max(|v|-THRESH, 0)
#pragma unroll
    for (int p = 0; p < 8; p++) {
        float lo[8], hi[8];
#pragma unroll
        for (int j = 0; j < 8; j++) unpack2(acc[p][j], lo[j], hi[j]);
        const int r0 = m0 + ty * 16 + 2 * p;
        const int col = n0 + tx * 8;
#pragma unroll
        for (int h = 0; h < 2; h++) {
            const int row = r0 + h;
            const float* vals = h ? hi : lo;
            float* cptr = alpha + (size_t)row * DICT + col;
#pragma unroll
            for (int j = 0; j < 8; j += 4) {
                float4 oldv;
                if (FIRST) { oldv.x = oldv.y = oldv.z = oldv.w = 0.0f; }
                else       { oldv = *reinterpret_cast<const float4*>(cptr + j); }
                float4 o;
                float v, s;
                v = oldv.x + STEP_SZ * vals[j + 0]; s = fabsf(v) - THRESH; o.x = s > 0.0f ? copysignf(s, v) : 0.0f;
                v = oldv.y + STEP_SZ * vals[j + 1]; s = fabsf(v) - THRESH; o.y = s > 0.0f ? copysignf(s, v) : 0.0f;
                v = oldv.z + STEP_SZ * vals[j + 2]; s = fabsf(v) - THRESH; o.z = s > 0.0f ? copysignf(s, v) : 0.0f;
                v = oldv.w + STEP_SZ * vals[j + 3]; s = fabsf(v) - THRESH; o.w = s > 0.0f ? copysignf(s, v) : 0.0f;
                *reinterpret_cast<float4*>(cptr + j) = o;
            }
        }
    }
}

// ---------------- iter 0: resid = X ----------------
__global__ void copy_resid_kernel(const float* __restrict__ X)
{
    int i = blockIdx.x * blockDim.x + threadIdx.x;
    const int n4 = (B_ROWS * EXP_DIM) / 4;
    if (i < n4) {
        reinterpret_cast<float4*>(g_resid)[i] =
            reinterpret_cast<const float4*>(X)[i];
    }
}

// ---------------- top-k (nibble radix select per row) ----------------
__global__ __launch_bounds__(256)
void topk_kernel(float* __restrict__ alpha)
{
    __shared__ unsigned int keys[DICT];
    __shared__ int hist[16];
    __shared__ int s_bucket;
    __shared__ int s_remk;

    const int tid = threadIdx.x;
    float* a = alpha + (size_t)blockIdx.x * DICT;

    for (int i = tid; i < DICT; i += 256)
        keys[i] = __float_as_uint(fabsf(a[i]));
    __syncthreads();

    unsigned int prefix = 0u, mask = 0u;
    int remk = K_SPARSE;

#pragma unroll
    for (int shift = 28; shift >= 0; shift -= 4) {
        if (tid < 16) hist[tid] = 0;
        __syncthreads();
        for (int i = tid; i < DICT; i += 256) {
            unsigned int k = keys[i];
            if ((k & mask) == prefix)
                atomicAdd(&hist[(k >> shift) & 15], 1);
        }
        __syncthreads();
        if (tid == 0) {
            int r = remk, b = 15;
            for (; b > 0; b--) {
                if (r - hist[b] <= 0) break;
                r -= hist[b];
            }
            s_bucket = b; s_remk = r;
        }
        __syncthreads();
        prefix |= ((unsigned int)s_bucket) << shift;
        mask   |= 0xFu << shift;
        remk = s_remk;
        __syncthreads();
    }

    const unsigned int t = prefix;
    for (int i = tid; i < DICT; i += 256)
        if (keys[i] < t) a[i] = 0.0f;
}

// ---------------- launch ----------------
extern "C" void kernel_launch(void* const* d_in, const int* in_sizes, int n_in,
                              void* d_out, int out_size)
{
    const float* X    = (const float*)d_in[0];   // [8192, 1024]
    const float* Dmat = (const float*)d_in[1];   // [4096, 1024]
    float* alpha      = (float*)d_out;           // [8192, 4096]

    const dim3 blk(NTHREADS);
    const dim3 g1(EXP_DIM / TN, B_ROWS / TM);    // ( 8, 32)
    const dim3 g2(DICT    / TN, B_ROWS / TM);    // (32, 32)

    // iter 0: alpha = 0 -> resid = X, then first alpha update
    {
        const int n4 = (B_ROWS * EXP_DIM) / 4;
        copy_resid_kernel<<<(n4 + 255) / 256, 256>>>(X);
        gemm2_kernel<true><<<g2, blk>>>(Dmat, alpha);
    }
    // iterations 1..19
    for (int it = 1; it < N_ITERS; it++) {
        gemm1_kernel<<<g1, blk>>>(alpha, Dmat, X);
        gemm2_kernel<false><<<g2, blk>>>(Dmat, alpha);
    }
    // hard top-k sparsification
    topk_kernel<<<B_ROWS, blk>>>(alpha);
}